// round 9
// baseline (speedup 1.0000x reference)
#include <cuda_runtime.h>
#include <cuda_fp16.h>
#include <cstdint>

#define D_DIM 1024
#define H_DIM 2048
#define E_NUM 8
#define T_MAX 4096
#define BM 128
#define MAX_TILES 72
#define MAX_ROWS  (MAX_TILES * BM)

#define BKW 64                /* fp16 K elems per stage */
#define UP_NK 16              /* D/BKW */
#define DN_NK 32              /* H/BKW */
#define STAGE_BYTES 49152
#define NSTAGE 4
#define GEMM_SMEM (NSTAGE * STAGE_BYTES + 1024)   /* 197632 */
#define RT_CTAS 512           /* router CTAs inside the merged prologue */

// ---------------- device-global scratch ------------------------------------
__device__ int   g_counts[E_NUM];
__device__ int   g_tile_expert[MAX_TILES];
__device__ int   g_list[E_NUM * T_MAX];
__device__ float g_probs[2 * T_MAX];
__device__ int   g_gather[MAX_ROWS];
__device__ int   g_row_of[2 * T_MAX];
__device__ __half g_xH [(size_t)T_MAX * D_DIM];
__device__ __half g_w1H[(size_t)E_NUM * H_DIM * D_DIM];
__device__ __half g_w2H[(size_t)E_NUM * H_DIM * D_DIM];
__device__ __half g_w3H[(size_t)E_NUM * D_DIM * H_DIM];
__device__ __half g_hH [(size_t)MAX_ROWS * H_DIM];
__device__ float g_y[(size_t)MAX_ROWS * D_DIM];

// ---------------- helpers ----------------------------------------------------
__device__ __forceinline__ uint32_t smem_u32(const void* p) {
    uint32_t a;
    asm("{ .reg .u64 t; cvta.to.shared.u64 t, %1; cvt.u32.u64 %0, t; }"
        : "=r"(a) : "l"(p));
    return a;
}
__device__ __forceinline__ void ldsm4(uint32_t& r0, uint32_t& r1, uint32_t& r2,
                                      uint32_t& r3, uint32_t addr) {
    asm volatile("ldmatrix.sync.aligned.m8n8.x4.shared.b16 {%0,%1,%2,%3}, [%4];"
                 : "=r"(r0), "=r"(r1), "=r"(r2), "=r"(r3) : "r"(addr));
}
__device__ __forceinline__ void mma16816(float* c, const uint32_t* a,
                                         const uint32_t* b) {
    asm volatile(
        "mma.sync.aligned.m16n8k16.row.col.f32.f16.f16.f32 "
        "{%0,%1,%2,%3},{%4,%5,%6,%7},{%8,%9},{%0,%1,%2,%3};"
        : "+f"(c[0]), "+f"(c[1]), "+f"(c[2]), "+f"(c[3])
        : "r"(a[0]), "r"(a[1]), "r"(a[2]), "r"(a[3]), "r"(b[0]), "r"(b[1]));
}
__device__ __forceinline__ void cp16(uint32_t dst, const void* src, int srcsize) {
    asm volatile("cp.async.cg.shared.global [%0], [%1], 16, %2;"
                 :: "r"(dst), "l"(src), "r"(srcsize) : "memory");
}
#define CP_COMMIT asm volatile("cp.async.commit_group;" ::: "memory")
template <int N>
__device__ __forceinline__ void cp_wait() {
    asm volatile("cp.async.wait_group %0;" :: "n"(N) : "memory");
}
__device__ __forceinline__ float silu_f(float v) { return v / (1.0f + __expf(-v)); }
__device__ __forceinline__ int sw_off(int r, int c) {
    return r * 128 + ((c ^ (r & 7)) << 4);
}

// ---------------- K0: init ----------------------------------------------------
__global__ void init_kernel() {
    if (threadIdx.x < E_NUM) g_counts[threadIdx.x] = 0;
}

// ---------------- K1: merged prologue: router(+x->fp16) + conv(w1,w2,w3) ------
__global__ void prologue_kernel(const float* __restrict__ x,
                                const float* __restrict__ gw,
                                const float* __restrict__ w1,
                                const float* __restrict__ w2,
                                const float* __restrict__ w3,
                                int T, long n4each) {
    const int b = blockIdx.x;
    if (b >= RT_CTAS) {
        long i = (long)(b - RT_CTAS) * blockDim.x + threadIdx.x;
        const float* src;
        __half* dst;
        long j;
        if (i < n4each)           { src = w1; dst = g_w1H; j = i; }
        else if (i < 2 * n4each)  { src = w2; dst = g_w2H; j = i - n4each; }
        else if (i < 3 * n4each)  { src = w3; dst = g_w3H; j = i - 2 * n4each; }
        else return;
        long eb = j * 4;
        float4 v = *(const float4*)(src + eb);
        __half2 h0 = __floats2half2_rn(v.x, v.y);
        __half2 h1 = __floats2half2_rn(v.z, v.w);
        *(uint2*)(dst + eb) = make_uint2(*(uint32_t*)&h0, *(uint32_t*)&h1);
        return;
    }

    // router part: one warp per token, fused x->fp16
    int warp = b * (blockDim.x >> 5) + (threadIdx.x >> 5);
    int lane = threadIdx.x & 31;
    if (warp >= T) return;
    const float* xr = x + (size_t)warp * D_DIM;
    __half* xh = g_xH + (size_t)warp * D_DIM;

    float acc[E_NUM];
#pragma unroll
    for (int e = 0; e < E_NUM; e++) acc[e] = 0.0f;
#pragma unroll
    for (int i = 0; i < D_DIM / 128; i++) {
        int d = i * 128 + lane * 4;
        float4 xv = *(const float4*)(xr + d);
        __half2 h0 = __floats2half2_rn(xv.x, xv.y);
        __half2 h1 = __floats2half2_rn(xv.z, xv.w);
        *(uint2*)(xh + d) = make_uint2(*(uint32_t*)&h0, *(uint32_t*)&h1);
#pragma unroll
        for (int e = 0; e < E_NUM; e++) {
            float4 gv = *(const float4*)(gw + e * D_DIM + d);
            acc[e] += xv.x * gv.x + xv.y * gv.y + xv.z * gv.z + xv.w * gv.w;
        }
    }
#pragma unroll
    for (int e = 0; e < E_NUM; e++) {
#pragma unroll
        for (int off = 16; off > 0; off >>= 1)
            acc[e] += __shfl_xor_sync(0xFFFFFFFFu, acc[e], off);
    }
    if (lane == 0) {
        int e0 = 0; float s0 = acc[0];
#pragma unroll
        for (int e = 1; e < E_NUM; e++) if (acc[e] > s0) { s0 = acc[e]; e0 = e; }
        int e1 = -1; float s1 = -3.4e38f;
#pragma unroll
        for (int e = 0; e < E_NUM; e++)
            if (e != e0 && acc[e] > s1) { s1 = acc[e]; e1 = e; }
        float x1 = __expf(s1 - s0);
        float inv = 1.0f / (1.0f + x1);
        int t = warp;
        g_probs[2 * t] = inv;
        g_probs[2 * t + 1] = x1 * inv;
        int j0 = atomicAdd(&g_counts[e0], 1);
        g_list[e0 * T_MAX + j0] = (t << 1);
        int j1 = atomicAdd(&g_counts[e1], 1);
        g_list[e1 * T_MAX + j1] = (t << 1) | 1;
    }
}

// ---------------- K2: build (inline scan) --------------------------------------
__global__ void build_kernel() {
    __shared__ int s_exp, s_off, s_cnt;
    if (threadIdx.x == 0) {
        int off = 0, nt = 0, my_e = -1, my_off = 0, my_cnt = 0;
#pragma unroll
        for (int e = 0; e < E_NUM; e++) {
            int c = g_counts[e];
            int te = (c + BM - 1) / BM;
            if ((int)blockIdx.x >= nt && (int)blockIdx.x < nt + te) {
                my_e = e; my_off = off; my_cnt = c;
            }
            nt += te;
            off += te * BM;
        }
        g_tile_expert[blockIdx.x] = my_e;
        s_exp = my_e; s_off = my_off; s_cnt = my_cnt;
    }
    __syncthreads();
    int e = s_exp;
    int r = blockIdx.x * BM + threadIdx.x;
    if (e < 0) { g_gather[r] = -1; return; }
    int j = r - s_off;
    if (j < s_cnt) {
        int entry = g_list[e * T_MAX + j];
        g_gather[r] = entry >> 1;
        g_row_of[entry] = r;
    } else {
        g_gather[r] = -1;
    }
}

// ---------------- K3: up GEMM (R7-validated core) ------------------------------
__global__ void __launch_bounds__(256, 1) gemm_up_mma() {
    const int e = g_tile_expert[blockIdx.y];
    if (e < 0) return;
    extern __shared__ char raw[];
    char* dsm = (char*)(((uintptr_t)raw + 1023) & ~(uintptr_t)1023);
    __shared__ int sg[BM];
    const int tid = threadIdx.x;
    const int m0 = blockIdx.y * BM;
    const int bn0 = blockIdx.x * 128;
    if (tid < BM) sg[tid] = g_gather[m0 + tid];
    __syncthreads();
    const uint32_t sb = smem_u32(dsm);
    const int lane = tid & 31, wid = tid >> 5;
    const int wm = wid & 1, wn = wid >> 1;

    const char* asrc[4]; int asz[4]; int dA[4];
    const char* b1s[4];
    const size_t w2delta = (const char*)g_w2H - (const char*)g_w1H;
#pragma unroll
    for (int i = 0; i < 4; i++) {
        int idx = tid + i * 256;
        int r = idx >> 3, c = idx & 7;
        dA[i] = sw_off(r, c);
        int tok = sg[r];
        asrc[i] = (tok >= 0) ? (const char*)(g_xH + (size_t)tok * D_DIM + c * 8)
                             : (const char*)g_xH;
        asz[i] = (tok >= 0) ? 16 : 0;
        b1s[i] = (const char*)(g_w1H + ((size_t)e * H_DIM + bn0 + r) * D_DIM + c * 8);
    }

#define U_LOAD(KT) do {                                                         \
    const int _s = (KT) % NSTAGE;                                               \
    const uint32_t _b = sb + _s * STAGE_BYTES;                                  \
    const int _k = (KT) * (BKW * 2);                                            \
    _Pragma("unroll") for (int i = 0; i < 4; i++) {                             \
        cp16(_b + dA[i], asrc[i] + _k, asz[i]);                                 \
        cp16(_b + 16384 + dA[i], b1s[i] + _k, 16);                              \
        cp16(_b + 32768 + dA[i], b1s[i] + w2delta + _k, 16);                    \
    } } while (0)

    U_LOAD(0); CP_COMMIT;
    U_LOAD(1); CP_COMMIT;
    U_LOAD(2); CP_COMMIT;

    float cu[4][4][4], cv[4][4][4];
#pragma unroll
    for (int a = 0; a < 4; a++)
#pragma unroll
        for (int b = 0; b < 4; b++)
#pragma unroll
            for (int c = 0; c < 4; c++) { cu[a][b][c] = 0.0f; cv[a][b][c] = 0.0f; }

    for (int kt = 0; kt < UP_NK; kt++) {
        cp_wait<2>(); __syncthreads();
        if (kt + 3 < UP_NK) U_LOAD(kt + 3);
        CP_COMMIT;
        const uint32_t At  = sb + (kt % NSTAGE) * STAGE_BYTES;
        const uint32_t B1t = At + 16384;
        const uint32_t B2t = At + 32768;
#pragma unroll
        for (int ks = 0; ks < 4; ks++) {
            uint32_t a[4][4];
#pragma unroll
            for (int mi = 0; mi < 4; mi++) {
                int r = wm * 64 + mi * 16 + (lane & 15);
                int c = ks * 2 + (lane >> 4);
                ldsm4(a[mi][0], a[mi][1], a[mi][2], a[mi][3], At + sw_off(r, c));
            }
#pragma unroll
            for (int bj = 0; bj < 2; bj++) {
                int r = wn * 32 + bj * 16 + ((lane >> 4) << 3) + (lane & 7);
                int c = ks * 2 + ((lane >> 3) & 1);
                int off = sw_off(r, c);
                uint32_t q0, q1, q2, q3;
                ldsm4(q0, q1, q2, q3, B1t + off);
                { uint32_t b[2] = {q0, q1};
#pragma unroll
                  for (int mi = 0; mi < 4; mi++) mma16816(cu[mi][2 * bj], a[mi], b); }
                { uint32_t b[2] = {q2, q3};
#pragma unroll
                  for (int mi = 0; mi < 4; mi++) mma16816(cu[mi][2 * bj + 1], a[mi], b); }
                ldsm4(q0, q1, q2, q3, B2t + off);
                { uint32_t b[2] = {q0, q1};
#pragma unroll
                  for (int mi = 0; mi < 4; mi++) mma16816(cv[mi][2 * bj], a[mi], b); }
                { uint32_t b[2] = {q2, q3};
#pragma unroll
                  for (int mi = 0; mi < 4; mi++) mma16816(cv[mi][2 * bj + 1], a[mi], b); }
            }
        }
    }
#undef U_LOAD

#pragma unroll
    for (int mi = 0; mi < 4; mi++) {
#pragma unroll
        for (int nj = 0; nj < 4; nj++) {
            int r0 = m0 + wm * 64 + mi * 16 + (lane >> 2);
            int col = bn0 + wn * 32 + nj * 8 + (lane & 3) * 2;
#pragma unroll
            for (int h = 0; h < 2; h++) {
                int r = r0 + 8 * h;
                float f0 = silu_f(cu[mi][nj][2 * h])     * cv[mi][nj][2 * h];
                float f1 = silu_f(cu[mi][nj][2 * h + 1]) * cv[mi][nj][2 * h + 1];
                __half2 hh = __floats2half2_rn(f0, f1);
                *(__half2*)(g_hH + (size_t)r * H_DIM + col) = hh;
            }
        }
    }
}

// ---------------- K4: down GEMM (R7-validated core) ----------------------------
__global__ void __launch_bounds__(256, 1) gemm_down_mma() {
    const int e = g_tile_expert[blockIdx.y];
    if (e < 0) return;
    extern __shared__ char raw[];
    char* dsm = (char*)(((uintptr_t)raw + 1023) & ~(uintptr_t)1023);
    const int tid = threadIdx.x;
    const int m0 = blockIdx.y * BM;
    const int bn0 = blockIdx.x * 256;
    const uint32_t sb = smem_u32(dsm);
    const int lane = tid & 31, wid = tid >> 5;
    const int wm = wid & 1, wn = wid >> 1;

    const char* asrc[4]; int dA[4];
    const char* bsrc[8]; int dB[8];
#pragma unroll
    for (int i = 0; i < 4; i++) {
        int idx = tid + i * 256;
        int r = idx >> 3, c = idx & 7;
        dA[i] = sw_off(r, c);
        asrc[i] = (const char*)(g_hH + (size_t)(m0 + r) * H_DIM + c * 8);
    }
#pragma unroll
    for (int i = 0; i < 8; i++) {
        int idx = tid + i * 256;
        int r = idx >> 3, c = idx & 7;
        dB[i] = sw_off(r, c);
        bsrc[i] = (const char*)(g_w3H + ((size_t)e * D_DIM + bn0 + r) * H_DIM + c * 8);
    }

#define D_LOAD(KT) do {                                                         \
    const int _s = (KT) % NSTAGE;                                               \
    const uint32_t _b = sb + _s * STAGE_BYTES;                                  \
    const long _k = (long)(KT) * (BKW * 2);                                     \
    _Pragma("unroll") for (int i = 0; i < 4; i++)                               \
        cp16(_b + dA[i], asrc[i] + _k, 16);                                     \
    _Pragma("unroll") for (int i = 0; i < 8; i++)                               \
        cp16(_b + 16384 + dB[i], bsrc[i] + _k, 16);                             \
    } while (0)

    D_LOAD(0); CP_COMMIT;
    D_LOAD(1); CP_COMMIT;
    D_LOAD(2); CP_COMMIT;

    float acc[4][8][4];
#pragma unroll
    for (int a = 0; a < 4; a++)
#pragma unroll
        for (int b = 0; b < 8; b++)
#pragma unroll
            for (int c = 0; c < 4; c++) acc[a][b][c] = 0.0f;

    for (int kt = 0; kt < DN_NK; kt++) {
        cp_wait<2>(); __syncthreads();
        if (kt + 3 < DN_NK) D_LOAD(kt + 3);
        CP_COMMIT;
        const uint32_t At = sb + (kt % NSTAGE) * STAGE_BYTES;
        const uint32_t Bt = At + 16384;
#pragma unroll
        for (int ks = 0; ks < 4; ks++) {
            uint32_t a[4][4];
#pragma unroll
            for (int mi = 0; mi < 4; mi++) {
                int r = wm * 64 + mi * 16 + (lane & 15);
                int c = ks * 2 + (lane >> 4);
                ldsm4(a[mi][0], a[mi][1], a[mi][2], a[mi][3], At + sw_off(r, c));
            }
#pragma unroll
            for (int bj = 0; bj < 4; bj++) {
                int r = wn * 64 + bj * 16 + ((lane >> 4) << 3) + (lane & 7);
                int c = ks * 2 + ((lane >> 3) & 1);
                uint32_t q0, q1, q2, q3;
                ldsm4(q0, q1, q2, q3, Bt + sw_off(r, c));
                { uint32_t b[2] = {q0, q1};
#pragma unroll
                  for (int mi = 0; mi < 4; mi++) mma16816(acc[mi][2 * bj], a[mi], b); }
                { uint32_t b[2] = {q2, q3};
#pragma unroll
                  for (int mi = 0; mi < 4; mi++) mma16816(acc[mi][2 * bj + 1], a[mi], b); }
            }
        }
    }
#undef D_LOAD

#pragma unroll
    for (int mi = 0; mi < 4; mi++) {
#pragma unroll
        for (int nj = 0; nj < 8; nj++) {
            int r0 = m0 + wm * 64 + mi * 16 + (lane >> 2);
            int col = bn0 + wn * 64 + nj * 8 + (lane & 3) * 2;
            float2 lo = make_float2(acc[mi][nj][0], acc[mi][nj][1]);
            float2 hi = make_float2(acc[mi][nj][2], acc[mi][nj][3]);
            *(float2*)(g_y + (size_t)r0 * D_DIM + col)       = lo;
            *(float2*)(g_y + (size_t)(r0 + 8) * D_DIM + col) = hi;
        }
    }
}

// ---------------- K5: combine ---------------------------------------------------
__global__ void combine_kernel(float* __restrict__ out, int T) {
    const int nq = D_DIM / 4;
    int idx = blockIdx.x * blockDim.x + threadIdx.x;
    if (idx >= T * nq) return;
    int t = idx / nq;
    int dq = idx - t * nq;
    int r0 = g_row_of[2 * t];
    int r1 = g_row_of[2 * t + 1];
    float p0 = g_probs[2 * t];
    float p1 = g_probs[2 * t + 1];
    float4 y0 = *(const float4*)&g_y[(size_t)r0 * D_DIM + dq * 4];
    float4 y1 = *(const float4*)&g_y[(size_t)r1 * D_DIM + dq * 4];
    float4 o;
    o.x = p0 * y0.x + p1 * y1.x;
    o.y = p0 * y0.y + p1 * y1.y;
    o.z = p0 * y0.z + p1 * y1.z;
    o.w = p0 * y0.w + p1 * y1.w;
    *(float4*)&out[(size_t)t * D_DIM + dq * 4] = o;
}

// ---------------- launch ---------------------------------------------------------
extern "C" void kernel_launch(void* const* d_in, const int* in_sizes, int n_in,
                              void* d_out, int out_size) {
    const float* x  = (const float*)d_in[0];
    const float* gw = (const float*)d_in[1];
    const float* w1 = (const float*)d_in[2];
    const float* w2 = (const float*)d_in[3];
    const float* w3 = (const float*)d_in[4];
    float* out = (float*)d_out;

    int T = in_sizes[0] / D_DIM;
    if (T > T_MAX) T = T_MAX;
    int m_tiles = (2 * T) / BM + E_NUM;
    if (m_tiles > MAX_TILES) m_tiles = MAX_TILES;

    cudaFuncSetAttribute(gemm_up_mma,   cudaFuncAttributeMaxDynamicSharedMemorySize, GEMM_SMEM);
    cudaFuncSetAttribute(gemm_down_mma, cudaFuncAttributeMaxDynamicSharedMemorySize, GEMM_SMEM);

    long n4each = (long)E_NUM * H_DIM * D_DIM / 4;   // per-tensor float4 count
    int conv_ctas = (int)((3 * n4each + 255) / 256);

    init_kernel<<<1, 32>>>();
    prologue_kernel<<<RT_CTAS + conv_ctas, 256>>>(x, gw, w1, w2, w3, T, n4each);
    build_kernel<<<m_tiles, BM>>>();
    gemm_up_mma<<<dim3(H_DIM / 128, m_tiles), 256, GEMM_SMEM>>>();
    gemm_down_mma<<<dim3(D_DIM / 256, m_tiles), 256, GEMM_SMEM>>>();
    combine_kernel<<<(T * (D_DIM / 4) + 255) / 256, 256>>>(out, T);
}

// round 10
// speedup vs baseline: 1.0963x; 1.0963x over previous
#include <cuda_runtime.h>
#include <cuda_fp16.h>
#include <cstdint>

#define D_DIM 1024
#define H_DIM 2048
#define E_NUM 8
#define T_MAX 4096
#define BM 128
#define MAX_TILES 72
#define MAX_ROWS  (MAX_TILES * BM)

#define BKW 64                /* fp16 K elems per stage */
#define UP_NK 16              /* D/BKW */
#define DN_NK 32              /* H/BKW */
#define STAGE_BYTES 49152     /* up: A16+B16+B16 ; down: A16+B32 */
#define NSTAGE 4
#define GEMM_SMEM (NSTAGE * STAGE_BYTES + 1024)   /* 197632 */

// ---------------- device-global scratch ------------------------------------
__device__ int   g_counts[E_NUM];
__device__ int   g_offsets[E_NUM + 1];
__device__ int   g_tile_expert[MAX_TILES];
__device__ int   g_list[E_NUM * T_MAX];
__device__ float g_probs[2 * T_MAX];
__device__ int   g_gather[MAX_ROWS];
__device__ int   g_row_of[2 * T_MAX];
__device__ __half g_xH [(size_t)T_MAX * D_DIM];
__device__ __half g_w1H[(size_t)E_NUM * H_DIM * D_DIM];
__device__ __half g_w2H[(size_t)E_NUM * H_DIM * D_DIM];
__device__ __half g_w3H[(size_t)E_NUM * D_DIM * H_DIM];
__device__ __half g_hH [(size_t)MAX_ROWS * H_DIM];
__device__ float g_y[(size_t)MAX_ROWS * D_DIM];

// ---------------- helpers ----------------------------------------------------
__device__ __forceinline__ uint32_t smem_u32(const void* p) {
    uint32_t a;
    asm("{ .reg .u64 t; cvta.to.shared.u64 t, %1; cvt.u32.u64 %0, t; }"
        : "=r"(a) : "l"(p));
    return a;
}
__device__ __forceinline__ void ldsm4(uint32_t& r0, uint32_t& r1, uint32_t& r2,
                                      uint32_t& r3, uint32_t addr) {
    asm volatile("ldmatrix.sync.aligned.m8n8.x4.shared.b16 {%0,%1,%2,%3}, [%4];"
                 : "=r"(r0), "=r"(r1), "=r"(r2), "=r"(r3) : "r"(addr));
}
__device__ __forceinline__ void mma16816(float* c, const uint32_t* a,
                                         const uint32_t* b) {
    asm volatile(
        "mma.sync.aligned.m16n8k16.row.col.f32.f16.f16.f32 "
        "{%0,%1,%2,%3},{%4,%5,%6,%7},{%8,%9},{%0,%1,%2,%3};"
        : "+f"(c[0]), "+f"(c[1]), "+f"(c[2]), "+f"(c[3])
        : "r"(a[0]), "r"(a[1]), "r"(a[2]), "r"(a[3]), "r"(b[0]), "r"(b[1]));
}
__device__ __forceinline__ void cp16(uint32_t dst, const void* src, int srcsize) {
    asm volatile("cp.async.cg.shared.global [%0], [%1], 16, %2;"
                 :: "r"(dst), "l"(src), "r"(srcsize) : "memory");
}
#define CP_COMMIT asm volatile("cp.async.commit_group;" ::: "memory")
template <int N>
__device__ __forceinline__ void cp_wait() {
    asm volatile("cp.async.wait_group %0;" :: "n"(N) : "memory");
}
__device__ __forceinline__ float silu_f(float v) { return v / (1.0f + __expf(-v)); }
__device__ __forceinline__ int sw_off(int r, int c) {
    return r * 128 + ((c ^ (r & 7)) << 4);
}

// ---------------- K0: init ----------------------------------------------------
__global__ void init_kernel() {
    if (threadIdx.x < E_NUM) g_counts[threadIdx.x] = 0;
}

// ---------------- K1: router (fused x->fp16), R7-validated --------------------
__global__ void router_kernel(const float* __restrict__ x,
                              const float* __restrict__ gw, int T) {
    int warp = blockIdx.x * (blockDim.x >> 5) + (threadIdx.x >> 5);
    int lane = threadIdx.x & 31;
    if (warp >= T) return;
    const float* xr = x + (size_t)warp * D_DIM;
    __half* xh = g_xH + (size_t)warp * D_DIM;

    float acc[E_NUM];
#pragma unroll
    for (int e = 0; e < E_NUM; e++) acc[e] = 0.0f;
#pragma unroll
    for (int i = 0; i < D_DIM / 128; i++) {
        int d = i * 128 + lane * 4;
        float4 xv = *(const float4*)(xr + d);
        __half2 h0 = __floats2half2_rn(xv.x, xv.y);
        __half2 h1 = __floats2half2_rn(xv.z, xv.w);
        *(uint2*)(xh + d) = make_uint2(*(uint32_t*)&h0, *(uint32_t*)&h1);
#pragma unroll
        for (int e = 0; e < E_NUM; e++) {
            float4 gv = *(const float4*)(gw + e * D_DIM + d);
            acc[e] += xv.x * gv.x + xv.y * gv.y + xv.z * gv.z + xv.w * gv.w;
        }
    }
#pragma unroll
    for (int e = 0; e < E_NUM; e++) {
#pragma unroll
        for (int off = 16; off > 0; off >>= 1)
            acc[e] += __shfl_xor_sync(0xFFFFFFFFu, acc[e], off);
    }
    if (lane == 0) {
        int e0 = 0; float s0 = acc[0];
#pragma unroll
        for (int e = 1; e < E_NUM; e++) if (acc[e] > s0) { s0 = acc[e]; e0 = e; }
        int e1 = -1; float s1 = -3.4e38f;
#pragma unroll
        for (int e = 0; e < E_NUM; e++)
            if (e != e0 && acc[e] > s1) { s1 = acc[e]; e1 = e; }
        float x1 = __expf(s1 - s0);
        float inv = 1.0f / (1.0f + x1);
        int t = warp;
        g_probs[2 * t] = inv;
        g_probs[2 * t + 1] = x1 * inv;
        int j0 = atomicAdd(&g_counts[e0], 1);
        g_list[e0 * T_MAX + j0] = (t << 1);
        int j1 = atomicAdd(&g_counts[e1], 1);
        g_list[e1 * T_MAX + j1] = (t << 1) | 1;
    }
}

// ---------------- K2/K3: scan + build (R7-validated) ---------------------------
__global__ void scan_kernel(int m_tiles_max) {
    if (threadIdx.x != 0 || blockIdx.x != 0) return;
    int off = 0, nt = 0;
    for (int e = 0; e < E_NUM; e++) {
        g_offsets[e] = off;
        int c = g_counts[e];
        int te = (c + BM - 1) / BM;
        for (int k = 0; k < te; k++) g_tile_expert[nt++] = e;
        off += te * BM;
    }
    g_offsets[E_NUM] = off;
    for (; nt < m_tiles_max; nt++) g_tile_expert[nt] = -1;
}

__global__ void build_kernel() {
    int tile = blockIdx.x;
    int e = g_tile_expert[tile];
    int r = tile * BM + threadIdx.x;
    if (e < 0) { g_gather[r] = -1; return; }
    int j = r - g_offsets[e];
    if (j < g_counts[e]) {
        int entry = g_list[e * T_MAX + j];
        g_gather[r] = entry >> 1;
        g_row_of[entry] = r;
    } else {
        g_gather[r] = -1;
    }
}

// ---------------- weight conversion: all three tensors, one launch (R7) --------
__global__ void conv_w_all_kernel(const float* __restrict__ w1,
                                  const float* __restrict__ w2,
                                  const float* __restrict__ w3, long n4) {
    long i = blockIdx.x * (long)blockDim.x + threadIdx.x;
    if (i >= 3 * n4) return;
    const float* src;
    __half* dst;
    long j;
    if (i < n4)           { src = w1; dst = g_w1H; j = i; }
    else if (i < 2 * n4)  { src = w2; dst = g_w2H; j = i - n4; }
    else                  { src = w3; dst = g_w3H; j = i - 2 * n4; }
    long eb = j * 4;
    float4 v = *(const float4*)(src + eb);
    __half2 h0 = __floats2half2_rn(v.x, v.y);
    __half2 h1 = __floats2half2_rn(v.z, v.w);
    *(uint2*)(dst + eb) = make_uint2(*(uint32_t*)&h0, *(uint32_t*)&h1);
}

// ---------------- K4: up GEMM — 512 threads, 16 warps (4m x 4n), warp 32x32 ----
__global__ void __launch_bounds__(512, 1) gemm_up_mma() {
    const int e = g_tile_expert[blockIdx.y];
    if (e < 0) return;
    extern __shared__ char raw[];
    char* dsm = (char*)(((uintptr_t)raw + 1023) & ~(uintptr_t)1023);
    __shared__ int sg[BM];
    const int tid = threadIdx.x;
    const int m0 = blockIdx.y * BM;
    const int bn0 = blockIdx.x * 128;
    if (tid < BM) sg[tid] = g_gather[m0 + tid];
    __syncthreads();
    const uint32_t sb = smem_u32(dsm);
    const int lane = tid & 31, wid = tid >> 5;
    const int wm = wid & 3, wn = wid >> 2;

    // staging: 1024 16B-chunks per tile, 512 threads -> 2 chunks each
    const char* asrc[2]; int asz[2]; int dA[2];
    const char* b1s[2];
    const size_t w2delta = (const char*)g_w2H - (const char*)g_w1H;
#pragma unroll
    for (int i = 0; i < 2; i++) {
        int idx = tid + i * 512;
        int r = idx >> 3, c = idx & 7;
        dA[i] = sw_off(r, c);
        int tok = sg[r];
        asrc[i] = (tok >= 0) ? (const char*)(g_xH + (size_t)tok * D_DIM + c * 8)
                             : (const char*)g_xH;
        asz[i] = (tok >= 0) ? 16 : 0;
        b1s[i] = (const char*)(g_w1H + ((size_t)e * H_DIM + bn0 + r) * D_DIM + c * 8);
    }

#define U_LOAD(KT) do {                                                         \
    const int _s = (KT) % NSTAGE;                                               \
    const uint32_t _b = sb + _s * STAGE_BYTES;                                  \
    const int _k = (KT) * (BKW * 2);                                            \
    _Pragma("unroll") for (int i = 0; i < 2; i++) {                             \
        cp16(_b + dA[i], asrc[i] + _k, asz[i]);                                 \
        cp16(_b + 16384 + dA[i], b1s[i] + _k, 16);                              \
        cp16(_b + 32768 + dA[i], b1s[i] + w2delta + _k, 16);                    \
    } } while (0)

    U_LOAD(0); CP_COMMIT;
    U_LOAD(1); CP_COMMIT;
    U_LOAD(2); CP_COMMIT;

    float cu[2][4][4], cv[2][4][4];
#pragma unroll
    for (int a = 0; a < 2; a++)
#pragma unroll
        for (int b = 0; b < 4; b++)
#pragma unroll
            for (int c = 0; c < 4; c++) { cu[a][b][c] = 0.0f; cv[a][b][c] = 0.0f; }

    for (int kt = 0; kt < UP_NK; kt++) {
        cp_wait<2>(); __syncthreads();
        if (kt + 3 < UP_NK) U_LOAD(kt + 3);
        CP_COMMIT;
        const uint32_t At  = sb + (kt % NSTAGE) * STAGE_BYTES;
        const uint32_t B1t = At + 16384;
        const uint32_t B2t = At + 32768;
#pragma unroll
        for (int ks = 0; ks < 4; ks++) {
            uint32_t a[2][4];
#pragma unroll
            for (int mi = 0; mi < 2; mi++) {
                int r = wm * 32 + mi * 16 + (lane & 15);
                int c = ks * 2 + (lane >> 4);
                ldsm4(a[mi][0], a[mi][1], a[mi][2], a[mi][3], At + sw_off(r, c));
            }
#pragma unroll
            for (int bj = 0; bj < 2; bj++) {
                int r = wn * 32 + bj * 16 + ((lane >> 4) << 3) + (lane & 7);
                int c = ks * 2 + ((lane >> 3) & 1);
                int off = sw_off(r, c);
                uint32_t q0, q1, q2, q3;
                ldsm4(q0, q1, q2, q3, B1t + off);
                { uint32_t b[2] = {q0, q1};
                  mma16816(cu[0][2 * bj], a[0], b); mma16816(cu[1][2 * bj], a[1], b); }
                { uint32_t b[2] = {q2, q3};
                  mma16816(cu[0][2 * bj + 1], a[0], b); mma16816(cu[1][2 * bj + 1], a[1], b); }
                ldsm4(q0, q1, q2, q3, B2t + off);
                { uint32_t b[2] = {q0, q1};
                  mma16816(cv[0][2 * bj], a[0], b); mma16816(cv[1][2 * bj], a[1], b); }
                { uint32_t b[2] = {q2, q3};
                  mma16816(cv[0][2 * bj + 1], a[0], b); mma16816(cv[1][2 * bj + 1], a[1], b); }
            }
        }
    }
#undef U_LOAD

    // epilogue: h = silu(u)*v -> fp16 -> g_hH
#pragma unroll
    for (int mi = 0; mi < 2; mi++) {
#pragma unroll
        for (int nj = 0; nj < 4; nj++) {
            int r0 = m0 + wm * 32 + mi * 16 + (lane >> 2);
            int col = bn0 + wn * 32 + nj * 8 + (lane & 3) * 2;
#pragma unroll
            for (int h = 0; h < 2; h++) {
                int r = r0 + 8 * h;
                float f0 = silu_f(cu[mi][nj][2 * h])     * cv[mi][nj][2 * h];
                float f1 = silu_f(cu[mi][nj][2 * h + 1]) * cv[mi][nj][2 * h + 1];
                __half2 hh = __floats2half2_rn(f0, f1);
                *(__half2*)(g_hH + (size_t)r * H_DIM + col) = hh;
            }
        }
    }
}

// ---------------- K5: down GEMM — 512 threads, 16 warps (4m x 4n), warp 32x64 --
__global__ void __launch_bounds__(512, 1) gemm_down_mma() {
    const int e = g_tile_expert[blockIdx.y];
    if (e < 0) return;
    extern __shared__ char raw[];
    char* dsm = (char*)(((uintptr_t)raw + 1023) & ~(uintptr_t)1023);
    const int tid = threadIdx.x;
    const int m0 = blockIdx.y * BM;
    const int bn0 = blockIdx.x * 256;
    const uint32_t sb = smem_u32(dsm);
    const int lane = tid & 31, wid = tid >> 5;
    const int wm = wid & 3, wn = wid >> 2;

    // staging: A 1024 chunks (2/thread), B 2048 chunks (4/thread)
    const char* asrc[2]; int dA[2];
    const char* bsrc[4]; int dB[4];
#pragma unroll
    for (int i = 0; i < 2; i++) {
        int idx = tid + i * 512;
        int r = idx >> 3, c = idx & 7;
        dA[i] = sw_off(r, c);
        asrc[i] = (const char*)(g_hH + (size_t)(m0 + r) * H_DIM + c * 8);
    }
#pragma unroll
    for (int i = 0; i < 4; i++) {
        int idx = tid + i * 512;
        int r = idx >> 3, c = idx & 7;
        dB[i] = sw_off(r, c);
        bsrc[i] = (const char*)(g_w3H + ((size_t)e * D_DIM + bn0 + r) * H_DIM + c * 8);
    }

#define D_LOAD(KT) do {                                                         \
    const int _s = (KT) % NSTAGE;                                               \
    const uint32_t _b = sb + _s * STAGE_BYTES;                                  \
    const long _k = (long)(KT) * (BKW * 2);                                     \
    _Pragma("unroll") for (int i = 0; i < 2; i++)                               \
        cp16(_b + dA[i], asrc[i] + _k, 16);                                     \
    _Pragma("unroll") for (int i = 0; i < 4; i++)                               \
        cp16(_b + 16384 + dB[i], bsrc[i] + _k, 16);                             \
    } while (0)

    D_LOAD(0); CP_COMMIT;
    D_LOAD(1); CP_COMMIT;
    D_LOAD(2); CP_COMMIT;

    float acc[2][8][4];
#pragma unroll
    for (int a = 0; a < 2; a++)
#pragma unroll
        for (int b = 0; b < 8; b++)
#pragma unroll
            for (int c = 0; c < 4; c++) acc[a][b][c] = 0.0f;

    for (int kt = 0; kt < DN_NK; kt++) {
        cp_wait<2>(); __syncthreads();
        if (kt + 3 < DN_NK) D_LOAD(kt + 3);
        CP_COMMIT;
        const uint32_t At = sb + (kt % NSTAGE) * STAGE_BYTES;
        const uint32_t Bt = At + 16384;
#pragma unroll
        for (int ks = 0; ks < 4; ks++) {
            uint32_t a[2][4];
#pragma unroll
            for (int mi = 0; mi < 2; mi++) {
                int r = wm * 32 + mi * 16 + (lane & 15);
                int c = ks * 2 + (lane >> 4);
                ldsm4(a[mi][0], a[mi][1], a[mi][2], a[mi][3], At + sw_off(r, c));
            }
#pragma unroll
            for (int bj = 0; bj < 4; bj++) {
                int r = wn * 64 + bj * 16 + ((lane >> 4) << 3) + (lane & 7);
                int c = ks * 2 + ((lane >> 3) & 1);
                uint32_t q0, q1, q2, q3;
                ldsm4(q0, q1, q2, q3, Bt + sw_off(r, c));
                { uint32_t b[2] = {q0, q1};
                  mma16816(acc[0][2 * bj], a[0], b); mma16816(acc[1][2 * bj], a[1], b); }
                { uint32_t b[2] = {q2, q3};
                  mma16816(acc[0][2 * bj + 1], a[0], b); mma16816(acc[1][2 * bj + 1], a[1], b); }
            }
        }
    }
#undef D_LOAD

#pragma unroll
    for (int mi = 0; mi < 2; mi++) {
#pragma unroll
        for (int nj = 0; nj < 8; nj++) {
            int r0 = m0 + wm * 32 + mi * 16 + (lane >> 2);
            int col = bn0 + wn * 64 + nj * 8 + (lane & 3) * 2;
            float2 lo = make_float2(acc[mi][nj][0], acc[mi][nj][1]);
            float2 hi = make_float2(acc[mi][nj][2], acc[mi][nj][3]);
            *(float2*)(g_y + (size_t)r0 * D_DIM + col)       = lo;
            *(float2*)(g_y + (size_t)(r0 + 8) * D_DIM + col) = hi;
        }
    }
}

// ---------------- K6: combine ---------------------------------------------------
__global__ void combine_kernel(float* __restrict__ out, int T) {
    const int nq = D_DIM / 4;
    int idx = blockIdx.x * blockDim.x + threadIdx.x;
    if (idx >= T * nq) return;
    int t = idx / nq;
    int dq = idx - t * nq;
    int r0 = g_row_of[2 * t];
    int r1 = g_row_of[2 * t + 1];
    float p0 = g_probs[2 * t];
    float p1 = g_probs[2 * t + 1];
    float4 y0 = *(const float4*)&g_y[(size_t)r0 * D_DIM + dq * 4];
    float4 y1 = *(const float4*)&g_y[(size_t)r1 * D_DIM + dq * 4];
    float4 o;
    o.x = p0 * y0.x + p1 * y1.x;
    o.y = p0 * y0.y + p1 * y1.y;
    o.z = p0 * y0.z + p1 * y1.z;
    o.w = p0 * y0.w + p1 * y1.w;
    *(float4*)&out[(size_t)t * D_DIM + dq * 4] = o;
}

// ---------------- launch ---------------------------------------------------------
extern "C" void kernel_launch(void* const* d_in, const int* in_sizes, int n_in,
                              void* d_out, int out_size) {
    const float* x  = (const float*)d_in[0];
    const float* gw = (const float*)d_in[1];
    const float* w1 = (const float*)d_in[2];
    const float* w2 = (const float*)d_in[3];
    const float* w3 = (const float*)d_in[4];
    float* out = (float*)d_out;

    int T = in_sizes[0] / D_DIM;
    if (T > T_MAX) T = T_MAX;
    int m_tiles = (2 * T) / BM + E_NUM;
    if (m_tiles > MAX_TILES) m_tiles = MAX_TILES;

    cudaFuncSetAttribute(gemm_up_mma,   cudaFuncAttributeMaxDynamicSharedMemorySize, GEMM_SMEM);
    cudaFuncSetAttribute(gemm_down_mma, cudaFuncAttributeMaxDynamicSharedMemorySize, GEMM_SMEM);

    init_kernel<<<1, 32>>>();
    router_kernel<<<(T + 7) / 8, 256>>>(x, gw, T);
    scan_kernel<<<1, 32>>>(m_tiles);
    build_kernel<<<m_tiles, BM>>>();

    long n4 = (long)E_NUM * H_DIM * D_DIM / 4;
    conv_w_all_kernel<<<(int)((3 * n4 + 255) / 256), 256>>>(w1, w2, w3, n4);

    gemm_up_mma<<<dim3(H_DIM / 128, m_tiles), 512, GEMM_SMEM>>>();
    gemm_down_mma<<<dim3(D_DIM / 256, m_tiles), 512, GEMM_SMEM>>>();
    combine_kernel<<<(T * (D_DIM / 4) + 255) / 256, 256>>>(out, T);
}

// round 11
// speedup vs baseline: 1.1161x; 1.0181x over previous
#include <cuda_runtime.h>
#include <cuda_fp16.h>
#include <cstdint>

#define D_DIM 1024
#define H_DIM 2048
#define E_NUM 8
#define T_MAX 4096
#define BM 128
#define MAX_TILES 72
#define MAX_ROWS  (MAX_TILES * BM)

#define BKW 64
#define UP_NK 16
#define DN_NK 32
#define STAGE_BYTES 49152
#define NSTAGE 4
#define GEMM_SMEM (NSTAGE * STAGE_BYTES + 1024)

// ---------------- device-global scratch ------------------------------------
__device__ int   g_counts[E_NUM];
__device__ int   g_tile_expert[MAX_TILES];
__device__ int   g_list[E_NUM * T_MAX];
__device__ float g_probs[2 * T_MAX];
__device__ int   g_gather[MAX_ROWS];
__device__ int   g_row_of[2 * T_MAX];
__device__ __half g_xH [(size_t)T_MAX * D_DIM];
__device__ __half g_w1H[(size_t)E_NUM * H_DIM * D_DIM];
__device__ __half g_w2H[(size_t)E_NUM * H_DIM * D_DIM];
__device__ __half g_w3H[(size_t)E_NUM * D_DIM * H_DIM];
__device__ __half g_hH [(size_t)MAX_ROWS * H_DIM];
__device__ float g_y[(size_t)MAX_ROWS * D_DIM];

// ---------------- helpers ----------------------------------------------------
__device__ __forceinline__ uint32_t smem_u32(const void* p) {
    uint32_t a;
    asm("{ .reg .u64 t; cvta.to.shared.u64 t, %1; cvt.u32.u64 %0, t; }"
        : "=r"(a) : "l"(p));
    return a;
}
__device__ __forceinline__ void ldsm4(uint32_t& r0, uint32_t& r1, uint32_t& r2,
                                      uint32_t& r3, uint32_t addr) {
    asm volatile("ldmatrix.sync.aligned.m8n8.x4.shared.b16 {%0,%1,%2,%3}, [%4];"
                 : "=r"(r0), "=r"(r1), "=r"(r2), "=r"(r3) : "r"(addr));
}
__device__ __forceinline__ void mma16816(float* c, const uint32_t* a,
                                         const uint32_t* b) {
    asm volatile(
        "mma.sync.aligned.m16n8k16.row.col.f32.f16.f16.f32 "
        "{%0,%1,%2,%3},{%4,%5,%6,%7},{%8,%9},{%0,%1,%2,%3};"
        : "+f"(c[0]), "+f"(c[1]), "+f"(c[2]), "+f"(c[3])
        : "r"(a[0]), "r"(a[1]), "r"(a[2]), "r"(a[3]), "r"(b[0]), "r"(b[1]));
}
__device__ __forceinline__ void cp16(uint32_t dst, const void* src, int srcsize) {
    asm volatile("cp.async.cg.shared.global [%0], [%1], 16, %2;"
                 :: "r"(dst), "l"(src), "r"(srcsize) : "memory");
}
#define CP_COMMIT asm volatile("cp.async.commit_group;" ::: "memory")
template <int N>
__device__ __forceinline__ void cp_wait() {
    asm volatile("cp.async.wait_group %0;" :: "n"(N) : "memory");
}
__device__ __forceinline__ float silu_f(float v) { return v / (1.0f + __expf(-v)); }
__device__ __forceinline__ int sw_off(int r, int c) {
    return r * 128 + ((c ^ (r & 7)) << 4);
}

// ---------------- K0: init ----------------------------------------------------
__global__ void init_kernel() {
    if (threadIdx.x < E_NUM) g_counts[threadIdx.x] = 0;
}

// ---------------- K1: router (fused x->fp16) -----------------------------------
__global__ void router_kernel(const float* __restrict__ x,
                              const float* __restrict__ gw, int T) {
    int warp = blockIdx.x * (blockDim.x >> 5) + (threadIdx.x >> 5);
    int lane = threadIdx.x & 31;
    if (warp >= T) return;
    const float* xr = x + (size_t)warp * D_DIM;
    __half* xh = g_xH + (size_t)warp * D_DIM;

    float acc[E_NUM];
#pragma unroll
    for (int e = 0; e < E_NUM; e++) acc[e] = 0.0f;
#pragma unroll
    for (int i = 0; i < D_DIM / 128; i++) {
        int d = i * 128 + lane * 4;
        float4 xv = *(const float4*)(xr + d);
        __half2 h0 = __floats2half2_rn(xv.x, xv.y);
        __half2 h1 = __floats2half2_rn(xv.z, xv.w);
        *(uint2*)(xh + d) = make_uint2(*(uint32_t*)&h0, *(uint32_t*)&h1);
#pragma unroll
        for (int e = 0; e < E_NUM; e++) {
            float4 gv = *(const float4*)(gw + e * D_DIM + d);
            acc[e] += xv.x * gv.x + xv.y * gv.y + xv.z * gv.z + xv.w * gv.w;
        }
    }
#pragma unroll
    for (int e = 0; e < E_NUM; e++) {
#pragma unroll
        for (int off = 16; off > 0; off >>= 1)
            acc[e] += __shfl_xor_sync(0xFFFFFFFFu, acc[e], off);
    }
    if (lane == 0) {
        int e0 = 0; float s0 = acc[0];
#pragma unroll
        for (int e = 1; e < E_NUM; e++) if (acc[e] > s0) { s0 = acc[e]; e0 = e; }
        int e1 = -1; float s1 = -3.4e38f;
#pragma unroll
        for (int e = 0; e < E_NUM; e++)
            if (e != e0 && acc[e] > s1) { s1 = acc[e]; e1 = e; }
        float x1 = __expf(s1 - s0);
        float inv = 1.0f / (1.0f + x1);
        int t = warp;
        g_probs[2 * t] = inv;
        g_probs[2 * t + 1] = x1 * inv;
        int j0 = atomicAdd(&g_counts[e0], 1);
        g_list[e0 * T_MAX + j0] = (t << 1);
        int j1 = atomicAdd(&g_counts[e1], 1);
        g_list[e1 * T_MAX + j1] = (t << 1) | 1;
    }
}

// ---------------- K2: build (inline scan) --------------------------------------
__global__ void build_kernel() {
    __shared__ int s_exp, s_off, s_cnt;
    if (threadIdx.x == 0) {
        int off = 0, nt = 0, my_e = -1, my_off = 0, my_cnt = 0;
#pragma unroll
        for (int e = 0; e < E_NUM; e++) {
            int c = g_counts[e];
            int te = (c + BM - 1) / BM;
            if ((int)blockIdx.x >= nt && (int)blockIdx.x < nt + te) {
                my_e = e; my_off = off; my_cnt = c;
            }
            nt += te;
            off += te * BM;
        }
        g_tile_expert[blockIdx.x] = my_e;
        s_exp = my_e; s_off = my_off; s_cnt = my_cnt;
    }
    __syncthreads();
    int e = s_exp;
    int r = blockIdx.x * BM + threadIdx.x;
    if (e < 0) { g_gather[r] = -1; return; }
    int j = r - s_off;
    if (j < s_cnt) {
        int entry = g_list[e * T_MAX + j];
        g_gather[r] = entry >> 1;
        g_row_of[entry] = r;
    } else {
        g_gather[r] = -1;
    }
}

// ---------------- weight conversion: all three tensors, one launch -------------
__global__ void conv_w_all_kernel(const float* __restrict__ w1,
                                  const float* __restrict__ w2,
                                  const float* __restrict__ w3, long n4) {
    long i = blockIdx.x * (long)blockDim.x + threadIdx.x;
    if (i >= 3 * n4) return;
    const float* src;
    __half* dst;
    long j;
    if (i < n4)           { src = w1; dst = g_w1H; j = i; }
    else if (i < 2 * n4)  { src = w2; dst = g_w2H; j = i - n4; }
    else                  { src = w3; dst = g_w3H; j = i - 2 * n4; }
    long eb = j * 4;
    float4 v = *(const float4*)(src + eb);
    __half2 h0 = __floats2half2_rn(v.x, v.y);
    __half2 h1 = __floats2half2_rn(v.z, v.w);
    *(uint2*)(dst + eb) = make_uint2(*(uint32_t*)&h0, *(uint32_t*)&h1);
}

// ---------------- K4: up GEMM — 512 thr, 16 warps (4m x 4n), warp 32x32 --------
// A-fragment register double-buffer: load ks+1's A while ks's MMAs drain.
__global__ void __launch_bounds__(512, 1) gemm_up_mma() {
    const int e = g_tile_expert[blockIdx.y];
    if (e < 0) return;
    extern __shared__ char raw[];
    char* dsm = (char*)(((uintptr_t)raw + 1023) & ~(uintptr_t)1023);
    __shared__ int sg[BM];
    const int tid = threadIdx.x;
    const int m0 = blockIdx.y * BM;
    const int bn0 = blockIdx.x * 128;
    if (tid < BM) sg[tid] = g_gather[m0 + tid];
    __syncthreads();
    const uint32_t sb = smem_u32(dsm);
    const int lane = tid & 31, wid = tid >> 5;
    const int wm = wid & 3, wn = wid >> 2;

    const char* asrc[2]; int asz[2]; int dA[2];
    const char* b1s[2];
    const size_t w2delta = (const char*)g_w2H - (const char*)g_w1H;
#pragma unroll
    for (int i = 0; i < 2; i++) {
        int idx = tid + i * 512;
        int r = idx >> 3, c = idx & 7;
        dA[i] = sw_off(r, c);
        int tok = sg[r];
        asrc[i] = (tok >= 0) ? (const char*)(g_xH + (size_t)tok * D_DIM + c * 8)
                             : (const char*)g_xH;
        asz[i] = (tok >= 0) ? 16 : 0;
        b1s[i] = (const char*)(g_w1H + ((size_t)e * H_DIM + bn0 + r) * D_DIM + c * 8);
    }

#define U_LOAD(KT) do {                                                         \
    const int _s = (KT) % NSTAGE;                                               \
    const uint32_t _b = sb + _s * STAGE_BYTES;                                  \
    const int _k = (KT) * (BKW * 2);                                            \
    _Pragma("unroll") for (int i = 0; i < 2; i++) {                             \
        cp16(_b + dA[i], asrc[i] + _k, asz[i]);                                 \
        cp16(_b + 16384 + dA[i], b1s[i] + _k, 16);                              \
        cp16(_b + 32768 + dA[i], b1s[i] + w2delta + _k, 16);                    \
    } } while (0)

    U_LOAD(0); CP_COMMIT;
    U_LOAD(1); CP_COMMIT;
    U_LOAD(2); CP_COMMIT;

    float cu[2][4][4], cv[2][4][4];
#pragma unroll
    for (int a = 0; a < 2; a++)
#pragma unroll
        for (int b = 0; b < 4; b++)
#pragma unroll
            for (int c = 0; c < 4; c++) { cu[a][b][c] = 0.0f; cv[a][b][c] = 0.0f; }

    const int ar0 = wm * 32 + (lane & 15);       // A frag row base (mi adds 16)
    const int acs = (lane >> 4);                 // A frag col half

    for (int kt = 0; kt < UP_NK; kt++) {
        cp_wait<2>(); __syncthreads();
        if (kt + 3 < UP_NK) U_LOAD(kt + 3);
        CP_COMMIT;
        const uint32_t At  = sb + (kt % NSTAGE) * STAGE_BYTES;
        const uint32_t B1t = At + 16384;
        const uint32_t B2t = At + 32768;

        uint32_t afr[2][2][4];   // [buf][mi][4]
#pragma unroll
        for (int mi = 0; mi < 2; mi++)
            ldsm4(afr[0][mi][0], afr[0][mi][1], afr[0][mi][2], afr[0][mi][3],
                  At + sw_off(ar0 + mi * 16, acs));
#pragma unroll
        for (int ks = 0; ks < 4; ks++) {
            const int cb = ks & 1, nb = cb ^ 1;
            if (ks < 3) {
#pragma unroll
                for (int mi = 0; mi < 2; mi++)
                    ldsm4(afr[nb][mi][0], afr[nb][mi][1], afr[nb][mi][2], afr[nb][mi][3],
                          At + sw_off(ar0 + mi * 16, (ks + 1) * 2 + acs));
            }
#pragma unroll
            for (int bj = 0; bj < 2; bj++) {
                int r = wn * 32 + bj * 16 + ((lane >> 4) << 3) + (lane & 7);
                int c = ks * 2 + ((lane >> 3) & 1);
                int off = sw_off(r, c);
                uint32_t q0, q1, q2, q3;
                ldsm4(q0, q1, q2, q3, B1t + off);
                { uint32_t b[2] = {q0, q1};
                  mma16816(cu[0][2 * bj], afr[cb][0], b);
                  mma16816(cu[1][2 * bj], afr[cb][1], b); }
                { uint32_t b[2] = {q2, q3};
                  mma16816(cu[0][2 * bj + 1], afr[cb][0], b);
                  mma16816(cu[1][2 * bj + 1], afr[cb][1], b); }
                ldsm4(q0, q1, q2, q3, B2t + off);
                { uint32_t b[2] = {q0, q1};
                  mma16816(cv[0][2 * bj], afr[cb][0], b);
                  mma16816(cv[1][2 * bj], afr[cb][1], b); }
                { uint32_t b[2] = {q2, q3};
                  mma16816(cv[0][2 * bj + 1], afr[cb][0], b);
                  mma16816(cv[1][2 * bj + 1], afr[cb][1], b); }
            }
        }
    }
#undef U_LOAD

    // epilogue: h = silu(u)*v -> fp16 -> g_hH
#pragma unroll
    for (int mi = 0; mi < 2; mi++) {
#pragma unroll
        for (int nj = 0; nj < 4; nj++) {
            int r0 = m0 + wm * 32 + mi * 16 + (lane >> 2);
            int col = bn0 + wn * 32 + nj * 8 + (lane & 3) * 2;
#pragma unroll
            for (int h = 0; h < 2; h++) {
                int r = r0 + 8 * h;
                float f0 = silu_f(cu[mi][nj][2 * h])     * cv[mi][nj][2 * h];
                float f1 = silu_f(cu[mi][nj][2 * h + 1]) * cv[mi][nj][2 * h + 1];
                __half2 hh = __floats2half2_rn(f0, f1);
                *(__half2*)(g_hH + (size_t)r * H_DIM + col) = hh;
            }
        }
    }
}

// ---------------- K5: down GEMM — 512 thr, 16 warps (4m x 4n), warp 32x64 ------
__global__ void __launch_bounds__(512, 1) gemm_down_mma() {
    const int e = g_tile_expert[blockIdx.y];
    if (e < 0) return;
    extern __shared__ char raw[];
    char* dsm = (char*)(((uintptr_t)raw + 1023) & ~(uintptr_t)1023);
    const int tid = threadIdx.x;
    const int m0 = blockIdx.y * BM;
    const int bn0 = blockIdx.x * 256;
    const uint32_t sb = smem_u32(dsm);
    const int lane = tid & 31, wid = tid >> 5;
    const int wm = wid & 3, wn = wid >> 2;

    const char* asrc[2]; int dA[2];
    const char* bsrc[4]; int dB[4];
#pragma unroll
    for (int i = 0; i < 2; i++) {
        int idx = tid + i * 512;
        int r = idx >> 3, c = idx & 7;
        dA[i] = sw_off(r, c);
        asrc[i] = (const char*)(g_hH + (size_t)(m0 + r) * H_DIM + c * 8);
    }
#pragma unroll
    for (int i = 0; i < 4; i++) {
        int idx = tid + i * 512;
        int r = idx >> 3, c = idx & 7;
        dB[i] = sw_off(r, c);
        bsrc[i] = (const char*)(g_w3H + ((size_t)e * D_DIM + bn0 + r) * H_DIM + c * 8);
    }

#define D_LOAD(KT) do {                                                         \
    const int _s = (KT) % NSTAGE;                                               \
    const uint32_t _b = sb + _s * STAGE_BYTES;                                  \
    const long _k = (long)(KT) * (BKW * 2);                                     \
    _Pragma("unroll") for (int i = 0; i < 2; i++)                               \
        cp16(_b + dA[i], asrc[i] + _k, 16);                                     \
    _Pragma("unroll") for (int i = 0; i < 4; i++)                               \
        cp16(_b + 16384 + dB[i], bsrc[i] + _k, 16);                             \
    } while (0)

    D_LOAD(0); CP_COMMIT;
    D_LOAD(1); CP_COMMIT;
    D_LOAD(2); CP_COMMIT;

    float acc[2][8][4];
#pragma unroll
    for (int a = 0; a < 2; a++)
#pragma unroll
        for (int b = 0; b < 8; b++)
#pragma unroll
            for (int c = 0; c < 4; c++) acc[a][b][c] = 0.0f;

    const int ar0 = wm * 32 + (lane & 15);
    const int acs = (lane >> 4);

    for (int kt = 0; kt < DN_NK; kt++) {
        cp_wait<2>(); __syncthreads();
        if (kt + 3 < DN_NK) D_LOAD(kt + 3);
        CP_COMMIT;
        const uint32_t At = sb + (kt % NSTAGE) * STAGE_BYTES;
        const uint32_t Bt = At + 16384;

        uint32_t afr[2][2][4];
#pragma unroll
        for (int mi = 0; mi < 2; mi++)
            ldsm4(afr[0][mi][0], afr[0][mi][1], afr[0][mi][2], afr[0][mi][3],
                  At + sw_off(ar0 + mi * 16, acs));
#pragma unroll
        for (int ks = 0; ks < 4; ks++) {
            const int cb = ks & 1, nb = cb ^ 1;
            if (ks < 3) {
#pragma unroll
                for (int mi = 0; mi < 2; mi++)
                    ldsm4(afr[nb][mi][0], afr[nb][mi][1], afr[nb][mi][2], afr[nb][mi][3],
                          At + sw_off(ar0 + mi * 16, (ks + 1) * 2 + acs));
            }
#pragma unroll
            for (int bj = 0; bj < 4; bj++) {
                int r = wn * 64 + bj * 16 + ((lane >> 4) << 3) + (lane & 7);
                int c = ks * 2 + ((lane >> 3) & 1);
                uint32_t q0, q1, q2, q3;
                ldsm4(q0, q1, q2, q3, Bt + sw_off(r, c));
                { uint32_t b[2] = {q0, q1};
                  mma16816(acc[0][2 * bj], afr[cb][0], b);
                  mma16816(acc[1][2 * bj], afr[cb][1], b); }
                { uint32_t b[2] = {q2, q3};
                  mma16816(acc[0][2 * bj + 1], afr[cb][0], b);
                  mma16816(acc[1][2 * bj + 1], afr[cb][1], b); }
            }
        }
    }
#undef D_LOAD

#pragma unroll
    for (int mi = 0; mi < 2; mi++) {
#pragma unroll
        for (int nj = 0; nj < 8; nj++) {
            int r0 = m0 + wm * 32 + mi * 16 + (lane >> 2);
            int col = bn0 + wn * 64 + nj * 8 + (lane & 3) * 2;
            float2 lo = make_float2(acc[mi][nj][0], acc[mi][nj][1]);
            float2 hi = make_float2(acc[mi][nj][2], acc[mi][nj][3]);
            *(float2*)(g_y + (size_t)r0 * D_DIM + col)       = lo;
            *(float2*)(g_y + (size_t)(r0 + 8) * D_DIM + col) = hi;
        }
    }
}

// ---------------- K6: combine ---------------------------------------------------
__global__ void combine_kernel(float* __restrict__ out, int T) {
    const int nq = D_DIM / 4;
    int idx = blockIdx.x * blockDim.x + threadIdx.x;
    if (idx >= T * nq) return;
    int t = idx / nq;
    int dq = idx - t * nq;
    int r0 = g_row_of[2 * t];
    int r1 = g_row_of[2 * t + 1];
    float p0 = g_probs[2 * t];
    float p1 = g_probs[2 * t + 1];
    float4 y0 = *(const float4*)&g_y[(size_t)r0 * D_DIM + dq * 4];
    float4 y1 = *(const float4*)&g_y[(size_t)r1 * D_DIM + dq * 4];
    float4 o;
    o.x = p0 * y0.x + p1 * y1.x;
    o.y = p0 * y0.y + p1 * y1.y;
    o.z = p0 * y0.z + p1 * y1.z;
    o.w = p0 * y0.w + p1 * y1.w;
    *(float4*)&out[(size_t)t * D_DIM + dq * 4] = o;
}

// ---------------- launch ---------------------------------------------------------
extern "C" void kernel_launch(void* const* d_in, const int* in_sizes, int n_in,
                              void* d_out, int out_size) {
    const float* x  = (const float*)d_in[0];
    const float* gw = (const float*)d_in[1];
    const float* w1 = (const float*)d_in[2];
    const float* w2 = (const float*)d_in[3];
    const float* w3 = (const float*)d_in[4];
    float* out = (float*)d_out;

    int T = in_sizes[0] / D_DIM;
    if (T > T_MAX) T = T_MAX;
    int m_tiles = (2 * T) / BM + E_NUM;
    if (m_tiles > MAX_TILES) m_tiles = MAX_TILES;

    cudaFuncSetAttribute(gemm_up_mma,   cudaFuncAttributeMaxDynamicSharedMemorySize, GEMM_SMEM);
    cudaFuncSetAttribute(gemm_down_mma, cudaFuncAttributeMaxDynamicSharedMemorySize, GEMM_SMEM);

    init_kernel<<<1, 32>>>();
    router_kernel<<<(T + 7) / 8, 256>>>(x, gw, T);
    build_kernel<<<m_tiles, BM>>>();

    long n4 = (long)E_NUM * H_DIM * D_DIM / 4;
    conv_w_all_kernel<<<(int)((3 * n4 + 255) / 256), 256>>>(w1, w2, w3, n4);

    gemm_up_mma<<<dim3(H_DIM / 128, m_tiles), 512, GEMM_SMEM>>>();
    gemm_down_mma<<<dim3(D_DIM / 256, m_tiles), 512, GEMM_SMEM>>>();
    combine_kernel<<<(T * (D_DIM / 4) + 255) / 256, 256>>>(out, T);
}